// round 5
// baseline (speedup 1.0000x reference)
#include <cuda_runtime.h>
#include <cuda_fp16.h>

// ---------------------------------------------------------------------------
// Popcnt_14731737825611 — R4: batch-tiled, L1-resident gather layers.
// CTA owns a 16-column batch tile (32B per activation row): slice fits L1,
// so the ~128x row reuse is serviced by L1 instead of the chip-wide L2 cap.
// Pair tables packed to 4B (u16 idx | fp16 weight), transposed [chunk][p][o],
// streamed via __ldcg (L1 bypass). LN stats fused into pop epilogue.
// ---------------------------------------------------------------------------

namespace {
constexpr int B    = 256;
constexpr int IN1  = 3200;
constexpr int O1   = 8192;
constexpr int O3   = 4096;
constexpr int P    = 128;
constexpr int BT   = 16;            // batch columns per tile (32B rows)
constexpr int NBT  = B / BT;        // 16 tiles
constexpr int OCH  = 1024;          // outputs per CTA
constexpr int NP1  = O1 / OCH;      // 8 chunks -> 8 LN partials
}

// Static device scratch.
__device__ __half   g_xT [IN1 * B];
__device__ __half   g_h1 [O1  * B];
__device__ __half   g_h2 [O1  * B];
__device__ __half   g_h3 [O3  * B];
__device__ unsigned g_pk1[O1 * P];     // packed (idx u16 | half w) [chunk][p][o]
__device__ unsigned g_pk2[O1 * P];
__device__ unsigned g_pk3[O3 * P];
__device__ float    g_C1b[O1];
__device__ float    g_C2b[O1];
__device__ float    g_C1c[O3];
__device__ float    g_C2c[O3];
__device__ float    g_ps[NP1 * B];
__device__ float    g_pq[NP1 * B];
__device__ float    g_mu[2][B];
__device__ float    g_rs[2][B];

__device__ __forceinline__ float sigmoidf_fast(float x) {
    return 1.0f / (1.0f + __expf(-x));
}
__device__ __forceinline__ unsigned pack_pair(int idx, float w) {
    __half h = __float2half_rn(w);
    return (unsigned)idx | ((unsigned)__half_as_ushort(h) << 16);
}

// --- transpose x[B, IN1] -> g_xT[IN1, B] (fp16) ----------------------------
__global__ void k_transpose(const float* __restrict__ x) {
    __shared__ float t[32][33];
    const int i0 = blockIdx.x * 32;
    const int b0 = blockIdx.y * 32;
    const int tx = threadIdx.x, ty = threadIdx.y;
#pragma unroll
    for (int j = 0; j < 32; j += 8)
        t[ty + j][tx] = x[(b0 + ty + j) * IN1 + (i0 + tx)];
    __syncthreads();
#pragma unroll
    for (int j = 0; j < 32; j += 8)
        g_xT[(i0 + ty + j) * B + (b0 + tx)] = __float2half_rn(t[tx][ty + j]);
}

// --- pack pair tables into transposed [chunk][p][o_local] layout -----------
// L==1: w' = sig(w).  L>1: w' = sig(w) * gamma[sel]  (input-LN fold).
template <int L>
__global__ void k_packT(const int* __restrict__ sel, const float* __restrict__ w,
                        const float* __restrict__ gamma) {
    unsigned* pk = (L == 1) ? g_pk1 : (L == 2) ? g_pk2 : g_pk3;
    __shared__ unsigned t[32][33];
    const int o0 = blockIdx.x * 32;
    const int p0 = blockIdx.y * 32;
    const int tx = threadIdx.x, ty = threadIdx.y;
#pragma unroll
    for (int j = 0; j < 32; j += 8) {
        const int o = o0 + ty + j;
        const int p = p0 + tx;
        const int   s  = __ldg(sel + o * P + p);
        const float wv = __ldg(w   + o * P + p);
        float sw = sigmoidf_fast(wv);
        if (L > 1) sw *= __ldg(gamma + s);
        t[tx][ty + j] = pack_pair(s, sw);
    }
    __syncthreads();
    const int chunk = o0 >> 10;              // OCH = 1024, o0 is 32-aligned
    const int obase = o0 & (OCH - 1);
#pragma unroll
    for (int j = 0; j < 32; j += 8) {
        const int p = p0 + ty + j;
        pk[chunk * (OCH * P) + p * OCH + obase + tx] = t[ty + j][tx];
    }
}

// --- C1/C2 constants for folded input-LN (layers 2,3): warp per output -----
template <int L>
__global__ void k_C(const int* __restrict__ sel, const float* __restrict__ w,
                    const float* __restrict__ gamma, const float* __restrict__ beta) {
    float* C1 = (L == 2) ? g_C1b : g_C1c;
    float* C2 = (L == 2) ? g_C2b : g_C2c;
    const int o    = blockIdx.x * 8 + (threadIdx.x >> 5);
    const int lane = threadIdx.x & 31;
    float c1 = 0.f, c2 = 0.f;
#pragma unroll
    for (int j = 0; j < 4; ++j) {
        const int   p  = lane + j * 32;
        const int   s  = __ldg(sel + o * P + p);
        const float sg = sigmoidf_fast(__ldg(w + o * P + p));
        c1 = fmaf(sg, __ldg(gamma + s), c1);
        c2 = fmaf(sg, __ldg(beta  + s), c2);
    }
#pragma unroll
    for (int st = 16; st > 0; st >>= 1) {
        c1 += __shfl_xor_sync(0xffffffffu, c1, st);
        c2 += __shfl_xor_sync(0xffffffffu, c2, st);
    }
    if (lane == 0) { C1[o] = c1; C2[o] = c2; }
}

// --- popcnt layer, b-tiled: thread = 1 output x 16 batch columns -----------
template <int L>
__global__ void __launch_bounds__(1024, 1) k_pop(const float* __restrict__ bias) {
    const __half*   inT  = (L == 1) ? g_xT  : (L == 2) ? g_h1  : g_h2;
    const unsigned* pk   = (L == 1) ? g_pk1 : (L == 2) ? g_pk2 : g_pk3;
    __half*         outT = (L == 1) ? g_h1  : (L == 2) ? g_h2  : g_h3;

    const int btile = blockIdx.x & (NBT - 1);
    const int chunk = blockIdx.x >> 4;
    const int ol    = threadIdx.x;
    const int o     = chunk * OCH + ol;
    const __half*   base = inT + btile * BT;            // column slice
    const unsigned* pp   = pk + chunk * (OCH * P) + ol;

    float acc[16];
#pragma unroll
    for (int j = 0; j < 16; ++j) acc[j] = 0.f;

#pragma unroll 4
    for (int p = 0; p < P; ++p) {
        const unsigned pr = __ldcg(pp + p * OCH);          // L1-bypass stream
        const float    wv = __half2float(__ushort_as_half((unsigned short)(pr >> 16)));
        const __half*  row = base + (pr & 0xFFFFu) * B;
        const uint4 v0 = __ldg((const uint4*)row);
        const uint4 v1 = __ldg((const uint4*)(row + 8));
        float2 f;
        f = __half22float2(*(const __half2*)&v0.x); acc[0] = fmaf(wv, f.x, acc[0]); acc[1] = fmaf(wv, f.y, acc[1]);
        f = __half22float2(*(const __half2*)&v0.y); acc[2] = fmaf(wv, f.x, acc[2]); acc[3] = fmaf(wv, f.y, acc[3]);
        f = __half22float2(*(const __half2*)&v0.z); acc[4] = fmaf(wv, f.x, acc[4]); acc[5] = fmaf(wv, f.y, acc[5]);
        f = __half22float2(*(const __half2*)&v0.w); acc[6] = fmaf(wv, f.x, acc[6]); acc[7] = fmaf(wv, f.y, acc[7]);
        f = __half22float2(*(const __half2*)&v1.x); acc[8] = fmaf(wv, f.x, acc[8]); acc[9] = fmaf(wv, f.y, acc[9]);
        f = __half22float2(*(const __half2*)&v1.y); acc[10] = fmaf(wv, f.x, acc[10]); acc[11] = fmaf(wv, f.y, acc[11]);
        f = __half22float2(*(const __half2*)&v1.z); acc[12] = fmaf(wv, f.x, acc[12]); acc[13] = fmaf(wv, f.y, acc[13]);
        f = __half22float2(*(const __half2*)&v1.w); acc[14] = fmaf(wv, f.x, acc[14]); acc[15] = fmaf(wv, f.y, acc[15]);
    }

    const float bo = bias[o];
    float h[16];
    if (L > 1) {
        const float c1 = ((L == 2) ? g_C1b : g_C1c)[o];
        const float c2 = ((L == 2) ? g_C2b : g_C2c)[o];
#pragma unroll
        for (int j = 0; j < 16; ++j) {
            const float mu = g_mu[L - 2][btile * BT + j];
            const float rs = g_rs[L - 2][btile * BT + j];
            h[j] = sigmoidf_fast(fmaf(rs, acc[j] - mu * c1, c2) - bo);
        }
    } else {
#pragma unroll
        for (int j = 0; j < 16; ++j) h[j] = sigmoidf_fast(acc[j] - bo);
    }

    // store fp16 activations (32B)
    {
        uint4 ov0, ov1;
        __half2 hh;
        hh = __floats2half2_rn(h[0], h[1]);  ov0.x = *(unsigned*)&hh;
        hh = __floats2half2_rn(h[2], h[3]);  ov0.y = *(unsigned*)&hh;
        hh = __floats2half2_rn(h[4], h[5]);  ov0.z = *(unsigned*)&hh;
        hh = __floats2half2_rn(h[6], h[7]);  ov0.w = *(unsigned*)&hh;
        hh = __floats2half2_rn(h[8], h[9]);  ov1.x = *(unsigned*)&hh;
        hh = __floats2half2_rn(h[10], h[11]); ov1.y = *(unsigned*)&hh;
        hh = __floats2half2_rn(h[12], h[13]); ov1.z = *(unsigned*)&hh;
        hh = __floats2half2_rn(h[14], h[15]); ov1.w = *(unsigned*)&hh;
        __half* orow = outT + o * B + btile * BT;
        *(uint4*)orow = ov0;
        *(uint4*)(orow + 8) = ov1;
    }

    // fused LN partial sums over this CTA's outputs (deterministic tree)
    if (L < 3) {
        float s[16], q[16];
#pragma unroll
        for (int j = 0; j < 16; ++j) { s[j] = h[j]; q[j] = h[j] * h[j]; }
#pragma unroll
        for (int st = 16; st > 0; st >>= 1) {
#pragma unroll
            for (int j = 0; j < 16; ++j) {
                s[j] += __shfl_xor_sync(0xffffffffu, s[j], st);
                q[j] += __shfl_xor_sync(0xffffffffu, q[j], st);
            }
        }
        __shared__ float ss[32][16], qq[32][16];
        const int wid = threadIdx.x >> 5, lane = threadIdx.x & 31;
        if (lane == 0) {
#pragma unroll
            for (int j = 0; j < 16; ++j) { ss[wid][j] = s[j]; qq[wid][j] = q[j]; }
        }
        __syncthreads();
        if (threadIdx.x < 16) {
            float ts = 0.f, tq = 0.f;
#pragma unroll
            for (int k = 0; k < 32; ++k) { ts += ss[k][threadIdx.x]; tq += qq[k][threadIdx.x]; }
            g_ps[chunk * B + btile * BT + threadIdx.x] = ts;
            g_pq[chunk * B + btile * BT + threadIdx.x] = tq;
        }
    }
}

// --- finalize LN stats: reduce NP1 partials per batch column ---------------
template <int L>
__global__ void k_ln_fin() {
    const int tid = threadIdx.x;
    float s = 0.f, q = 0.f;
#pragma unroll
    for (int i = 0; i < NP1; ++i) { s += g_ps[i * B + tid]; q += g_pq[i * B + tid]; }
    const float m   = s * (1.0f / O1);
    const float var = q * (1.0f / O1) - m * m;
    g_mu[L - 1][tid] = m;
    g_rs[L - 1][tid] = rsqrtf(var + 1e-12f);
}

// --- final: group-sum of 16 + bias, out[b, g] ------------------------------
__global__ void k_final(float* __restrict__ out) {
    const int gg = blockIdx.x;
    const int tid = threadIdx.x;
    float acc = 0.f;
#pragma unroll
    for (int j = 0; j < 16; ++j)
        acc += __half2float(g_h3[(gg * 16 + j) * B + tid]);
    out[tid * 256 + gg] = acc - 8.0f;
}

// ---------------------------------------------------------------------------
extern "C" void kernel_launch(void* const* d_in, const int* in_sizes, int n_in,
                              void* d_out, int out_size) {
    (void)in_sizes; (void)n_in; (void)out_size;
    const float* x    = (const float*)d_in[0];
    const int*   sel1 = (const int*)  d_in[1];
    const float* w1   = (const float*)d_in[2];
    const float* b1   = (const float*)d_in[3];
    const float* g1   = (const float*)d_in[4];
    const float* be1  = (const float*)d_in[5];
    const int*   sel2 = (const int*)  d_in[6];
    const float* w2   = (const float*)d_in[7];
    const float* b2   = (const float*)d_in[8];
    const float* g2   = (const float*)d_in[9];
    const float* be2  = (const float*)d_in[10];
    const int*   sel3 = (const int*)  d_in[11];
    const float* w3   = (const float*)d_in[12];
    const float* b3   = (const float*)d_in[13];
    float* out = (float*)d_out;

    k_transpose<<<dim3(IN1 / 32, B / 32), dim3(32, 8)>>>(x);
    k_packT<1><<<dim3(O1 / 32, P / 32), dim3(32, 8)>>>(sel1, w1, nullptr);
    k_packT<2><<<dim3(O1 / 32, P / 32), dim3(32, 8)>>>(sel2, w2, g1);
    k_packT<3><<<dim3(O3 / 32, P / 32), dim3(32, 8)>>>(sel3, w3, g2);
    k_C<2><<<O1 / 8, 256>>>(sel2, w2, g1, be1);
    k_C<3><<<O3 / 8, 256>>>(sel3, w3, g2, be2);

    k_pop<1><<<(O1 / OCH) * NBT, 1024>>>(b1);   // 128 CTAs
    k_ln_fin<1><<<1, 256>>>();
    k_pop<2><<<(O1 / OCH) * NBT, 1024>>>(b2);   // 128 CTAs
    k_ln_fin<2><<<1, 256>>>();
    k_pop<3><<<(O3 / OCH) * NBT, 1024>>>(b3);   // 64 CTAs
    k_final<<<256, 256>>>(out);
}

// round 8
// speedup vs baseline: 1.5315x; 1.5315x over previous
#include <cuda_runtime.h>
#include <cuda_fp16.h>

// ---------------------------------------------------------------------------
// Popcnt_14731737825611 — R5: smem-staged batch-sliced gather layers.
// Each CTA stages a batch slice (8 or 16 columns) of the whole activation
// table in shared memory; random-row gathers hit the smem crossbar (which
// tolerates divergence) instead of the chip-wide L2 cap. Pairs packed as
// (u16 idx | fp16 w) quads in [chunk][p/4][o] layout, streamed via __ldcg.
// LN folded into weights (C1/C2); LN-finalize fused into next pop prologue;
// final group-sum fused into pop<3>. 6 kernel launches total.
// ---------------------------------------------------------------------------

namespace {
constexpr int B   = 256;
constexpr int IN1 = 3200;
constexpr int O1  = 8192;
constexpr int O3  = 4096;
constexpr int P   = 128;
}

// Static device scratch.
__device__ __half g_xT [IN1 * B];
__device__ __half g_h1 [O1  * B];
__device__ __half g_h2 [O1  * B];
__device__ uint4  g_pk1[O1 * P / 4];   // quads: [chunk][p/4][o_local], OCH=1024
__device__ uint4  g_pk2[O1 * P / 4];   // OCH=2048
__device__ uint4  g_pk3[O3 * P / 4];   // OCH=1024
__device__ float  g_C1b[O1];
__device__ float  g_C2b[O1];
__device__ float  g_C1c[O3];
__device__ float  g_C2c[O3];
__device__ float  g_ps1[8 * B], g_pq1[8 * B];   // h1 LN partials (8 chunks)
__device__ float  g_ps2[4 * B], g_pq2[4 * B];   // h2 LN partials (4 chunks)

__device__ __forceinline__ float sigmoidf_fast(float x) {
    return 1.0f / (1.0f + __expf(-x));
}
__device__ __forceinline__ unsigned pack_pair(int idx, float w) {
    __half h = __float2half_rn(w);
    return (unsigned)idx | ((unsigned)__half_as_ushort(h) << 16);
}

// --- transpose x[B, IN1] -> g_xT[IN1, B] (fp16) ----------------------------
__global__ void k_transpose(const float* __restrict__ x) {
    __shared__ float t[32][33];
    const int i0 = blockIdx.x * 32;
    const int b0 = blockIdx.y * 32;
    const int tx = threadIdx.x, ty = threadIdx.y;
#pragma unroll
    for (int j = 0; j < 32; j += 8)
        t[ty + j][tx] = x[(b0 + ty + j) * IN1 + (i0 + tx)];
    __syncthreads();
#pragma unroll
    for (int j = 0; j < 32; j += 8)
        g_xT[(i0 + ty + j) * B + (b0 + tx)] = __float2half_rn(t[tx][ty + j]);
}

// --- merged prep: pack all 3 pair tables (+gamma fold), C1/C2 for L2/L3 ----
// Block = 1024 threads = 32 warps; warp = one output row (all 128 p's).
__global__ void __launch_bounds__(1024) k_prep(
    const int* __restrict__ sel1, const float* __restrict__ w1,
    const int* __restrict__ sel2, const float* __restrict__ w2,
    const float* __restrict__ g1v, const float* __restrict__ be1,
    const int* __restrict__ sel3, const float* __restrict__ w3,
    const float* __restrict__ g2v, const float* __restrict__ be2)
{
    __shared__ unsigned tile[128][33];
    const int blk = blockIdx.x;
    const int*   sel; const float* w; const float* gm; const float* bt;
    uint4* pk; float* C1; float* C2; int o0, OCH, layer;
    if (blk < 256)      { layer = 1; sel = sel1; w = w1; gm = nullptr; bt = nullptr;
                          pk = g_pk1; C1 = nullptr; C2 = nullptr; o0 = blk * 32;        OCH = 1024; }
    else if (blk < 512) { layer = 2; sel = sel2; w = w2; gm = g1v;   bt = be1;
                          pk = g_pk2; C1 = g_C1b; C2 = g_C2b; o0 = (blk - 256) * 32;   OCH = 2048; }
    else                { layer = 3; sel = sel3; w = w3; gm = g2v;   bt = be2;
                          pk = g_pk3; C1 = g_C1c; C2 = g_C2c; o0 = (blk - 512) * 32;   OCH = 1024; }

    const int wid = threadIdx.x >> 5, lane = threadIdx.x & 31;
    const int o = o0 + wid;
    const int4   s4 = reinterpret_cast<const int4*>(sel + o * P)[lane];
    const float4 w4 = reinterpret_cast<const float4*>(w   + o * P)[lane];
    const int   idx[4] = { s4.x, s4.y, s4.z, s4.w };
    const float sg[4]  = { sigmoidf_fast(w4.x), sigmoidf_fast(w4.y),
                           sigmoidf_fast(w4.z), sigmoidf_fast(w4.w) };
    float c1 = 0.f, c2 = 0.f;
#pragma unroll
    for (int j = 0; j < 4; ++j) {
        float sw = sg[j];
        if (layer > 1) {
            sw *= __ldg(gm + idx[j]);
            c1 += sw;
            c2 = fmaf(sg[j], __ldg(bt + idx[j]), c2);
        }
        tile[lane * 4 + j][wid] = pack_pair(idx[j], sw);
    }
    if (layer > 1) {
#pragma unroll
        for (int st = 16; st > 0; st >>= 1) {
            c1 += __shfl_xor_sync(0xffffffffu, c1, st);
            c2 += __shfl_xor_sync(0xffffffffu, c2, st);
        }
        if (lane == 0) { C1[o] = c1; C2[o] = c2; }
    }
    __syncthreads();
    // write phase: warp wid owns p-quad wid, lanes span the 32 outputs
    uint4 ov;
    ov.x = tile[wid * 4 + 0][lane];
    ov.y = tile[wid * 4 + 1][lane];
    ov.z = tile[wid * 4 + 2][lane];
    ov.w = tile[wid * 4 + 3][lane];
    const int chunk = o0 / OCH;
    const int obase = o0 % OCH;
    pk[chunk * (OCH * 32) + wid * OCH + obase + lane] = ov;
}

// --- popcnt layer, smem-staged ---------------------------------------------
// L=1: rows=3200, BT=16, OPT=1, OCH=1024, grid 16x8=128
// L=2: rows=8192, BT=8,  OPT=2, OCH=2048, grid 32x4=128
// L=3: rows=8192, BT=8,  OPT=1, OCH=1024, grid 32x4=128, fused group-sum out
template <int L>
__global__ void __launch_bounds__(1024, 1) k_pop(const float* __restrict__ bias,
                                                 float* __restrict__ out)
{
    constexpr int NR  = (L == 1) ? IN1 : O1;
    constexpr int BT  = (L == 1) ? 16 : 8;
    constexpr int NBT = B / BT;
    constexpr int OPT = (L == 2) ? 2 : 1;
    constexpr int OCH = 1024 * OPT;

    extern __shared__ unsigned char s_raw[];
    uint4* sl = reinterpret_cast<uint4*>(s_raw);     // slice: NR * (BT/8) uint4
    __shared__ float smu[16], srs[16];
    __shared__ float ssum[32][16], sqq[32][16];

    const __half* inT = (L == 1) ? g_xT : (L == 2) ? g_h1 : g_h2;
    const uint4*  pk  = (L == 1) ? g_pk1 : (L == 2) ? g_pk2 : g_pk3;
    __half*       outT = (L == 1) ? g_h1 : g_h2;     // unused for L==3

    const int btile = blockIdx.x % NBT;
    const int chunk = blockIdx.x / NBT;
    const int tid   = threadIdx.x;

    // stage batch slice into smem
    {
        const __half* base = inT + btile * BT;
        for (int r = tid; r < NR; r += 1024) {
            const uint4* src = reinterpret_cast<const uint4*>(base + r * B);
            if (BT == 8) {
                sl[r] = src[0];
            } else {
                sl[2 * r]     = src[0];
                sl[2 * r + 1] = src[1];
            }
        }
    }
    // fused LN finalize for the input of this layer
    if (L > 1 && tid < BT) {
        constexpr int NP = (L == 2) ? 8 : 4;
        const float* ps = (L == 2) ? g_ps1 : g_ps2;
        const float* pq = (L == 2) ? g_pq1 : g_pq2;
        const int col = btile * BT + tid;
        float s = 0.f, q = 0.f;
#pragma unroll
        for (int c = 0; c < NP; ++c) { s += ps[c * B + col]; q += pq[c * B + col]; }
        const float inv = 1.0f / (float)O1;
        const float m   = s * inv;
        const float var = q * inv - m * m;
        smu[tid] = m;
        srs[tid] = rsqrtf(var + 1e-12f);
    }
    __syncthreads();

    const int ol = tid;
    float acc0[BT];
    float acc1[(OPT == 2) ? BT : 1];
#pragma unroll
    for (int j = 0; j < BT; ++j) acc0[j] = 0.f;
    if (OPT == 2) {
#pragma unroll
        for (int j = 0; j < BT; ++j) acc1[j] = 0.f;
    }

    const uint4* pp = pk + chunk * (OCH * 32) + ol;
#pragma unroll 2
    for (int q = 0; q < 32; ++q) {
        const uint4 pra = __ldcg(pp + q * OCH);
        uint4 prb;
        if (OPT == 2) prb = __ldcg(pp + q * OCH + 1024);
        const unsigned pa[4] = { pra.x, pra.y, pra.z, pra.w };
#pragma unroll
        for (int j = 0; j < 4; ++j) {
            const unsigned pc = pa[j];
            const float wv = __half2float(__ushort_as_half((unsigned short)(pc >> 16)));
            const int row = (int)(pc & 0xFFFFu);
            if (BT == 8) {
                const uint4 v = sl[row];
                float2 f;
                f = __half22float2(*(const __half2*)&v.x); acc0[0] = fmaf(wv, f.x, acc0[0]); acc0[1] = fmaf(wv, f.y, acc0[1]);
                f = __half22float2(*(const __half2*)&v.y); acc0[2] = fmaf(wv, f.x, acc0[2]); acc0[3] = fmaf(wv, f.y, acc0[3]);
                f = __half22float2(*(const __half2*)&v.z); acc0[4] = fmaf(wv, f.x, acc0[4]); acc0[5] = fmaf(wv, f.y, acc0[5]);
                f = __half22float2(*(const __half2*)&v.w); acc0[6] = fmaf(wv, f.x, acc0[6]); acc0[7] = fmaf(wv, f.y, acc0[7]);
            } else {
                const uint4 v0 = sl[2 * row];
                const uint4 v1 = sl[2 * row + 1];
                float2 f;
                f = __half22float2(*(const __half2*)&v0.x); acc0[0]  = fmaf(wv, f.x, acc0[0]);  acc0[1]  = fmaf(wv, f.y, acc0[1]);
                f = __half22float2(*(const __half2*)&v0.y); acc0[2]  = fmaf(wv, f.x, acc0[2]);  acc0[3]  = fmaf(wv, f.y, acc0[3]);
                f = __half22float2(*(const __half2*)&v0.z); acc0[4]  = fmaf(wv, f.x, acc0[4]);  acc0[5]  = fmaf(wv, f.y, acc0[5]);
                f = __half22float2(*(const __half2*)&v0.w); acc0[6]  = fmaf(wv, f.x, acc0[6]);  acc0[7]  = fmaf(wv, f.y, acc0[7]);
                f = __half22float2(*(const __half2*)&v1.x); acc0[8]  = fmaf(wv, f.x, acc0[8]);  acc0[9]  = fmaf(wv, f.y, acc0[9]);
                f = __half22float2(*(const __half2*)&v1.y); acc0[10] = fmaf(wv, f.x, acc0[10]); acc0[11] = fmaf(wv, f.y, acc0[11]);
                f = __half22float2(*(const __half2*)&v1.z); acc0[12] = fmaf(wv, f.x, acc0[12]); acc0[13] = fmaf(wv, f.y, acc0[13]);
                f = __half22float2(*(const __half2*)&v1.w); acc0[14] = fmaf(wv, f.x, acc0[14]); acc0[15] = fmaf(wv, f.y, acc0[15]);
            }
        }
        if (OPT == 2) {
            const unsigned pb[4] = { prb.x, prb.y, prb.z, prb.w };
#pragma unroll
            for (int j = 0; j < 4; ++j) {
                const unsigned pc = pb[j];
                const float wv = __half2float(__ushort_as_half((unsigned short)(pc >> 16)));
                const int row = (int)(pc & 0xFFFFu);
                const uint4 v = sl[row];
                float2 f;
                f = __half22float2(*(const __half2*)&v.x); acc1[0] = fmaf(wv, f.x, acc1[0]); acc1[1] = fmaf(wv, f.y, acc1[1]);
                f = __half22float2(*(const __half2*)&v.y); acc1[2] = fmaf(wv, f.x, acc1[2]); acc1[3] = fmaf(wv, f.y, acc1[3]);
                f = __half22float2(*(const __half2*)&v.z); acc1[4] = fmaf(wv, f.x, acc1[4]); acc1[5] = fmaf(wv, f.y, acc1[5]);
                f = __half22float2(*(const __half2*)&v.w); acc1[6] = fmaf(wv, f.x, acc1[6]); acc1[7] = fmaf(wv, f.y, acc1[7]);
            }
        }
    }

    // epilogue: bias + (folded LN) + sigmoid
    const int o0 = chunk * OCH + ol;
    float h0[BT], h1v[(OPT == 2) ? BT : 1];
    {
        const float bo = bias[o0];
        float c1 = 0.f, c2 = 0.f;
        if (L > 1) { c1 = ((L == 2) ? g_C1b : g_C1c)[o0]; c2 = ((L == 2) ? g_C2b : g_C2c)[o0]; }
#pragma unroll
        for (int j = 0; j < BT; ++j) {
            float pre = (L > 1) ? (fmaf(srs[j], acc0[j] - smu[j] * c1, c2) - bo)
                                : (acc0[j] - bo);
            h0[j] = sigmoidf_fast(pre);
        }
    }
    if (OPT == 2) {
        const int o1 = o0 + 1024;
        const float bo = bias[o1];
        const float c1 = g_C1b[o1], c2 = g_C2b[o1];
#pragma unroll
        for (int j = 0; j < BT; ++j)
            h1v[j] = sigmoidf_fast(fmaf(srs[j], acc1[j] - smu[j] * c1, c2) - bo);
    }

    if (L < 3) {
        // store fp16 activations
        {
            __half* orow = outT + o0 * B + btile * BT;
            uint4 ov;
            __half2 hh;
            hh = __floats2half2_rn(h0[0], h0[1]); ov.x = *(unsigned*)&hh;
            hh = __floats2half2_rn(h0[2], h0[3]); ov.y = *(unsigned*)&hh;
            hh = __floats2half2_rn(h0[4], h0[5]); ov.z = *(unsigned*)&hh;
            hh = __floats2half2_rn(h0[6], h0[7]); ov.w = *(unsigned*)&hh;
            reinterpret_cast<uint4*>(orow)[0] = ov;
            if (BT == 16) {
                hh = __floats2half2_rn(h0[8],  h0[9]);  ov.x = *(unsigned*)&hh;
                hh = __floats2half2_rn(h0[10], h0[11]); ov.y = *(unsigned*)&hh;
                hh = __floats2half2_rn(h0[12], h0[13]); ov.z = *(unsigned*)&hh;
                hh = __floats2half2_rn(h0[14], h0[15]); ov.w = *(unsigned*)&hh;
                reinterpret_cast<uint4*>(orow)[1] = ov;
            }
            if (OPT == 2) {
                __half* orow1 = outT + (o0 + 1024) * B + btile * BT;
                hh = __floats2half2_rn(h1v[0], h1v[1]); ov.x = *(unsigned*)&hh;
                hh = __floats2half2_rn(h1v[2], h1v[3]); ov.y = *(unsigned*)&hh;
                hh = __floats2half2_rn(h1v[4], h1v[5]); ov.z = *(unsigned*)&hh;
                hh = __floats2half2_rn(h1v[6], h1v[7]); ov.w = *(unsigned*)&hh;
                reinterpret_cast<uint4*>(orow1)[0] = ov;
            }
        }
        // LN partial sums for this (chunk, btile)
        float s[16], q[16];
#pragma unroll
        for (int j = 0; j < BT; ++j) {
            float hv = h0[j];
            float sq = hv * hv;
            if (OPT == 2) { hv += h1v[j]; sq = fmaf(h1v[j], h1v[j], sq); }
            s[j] = hv; q[j] = sq;
        }
#pragma unroll
        for (int st = 16; st > 0; st >>= 1) {
#pragma unroll
            for (int j = 0; j < BT; ++j) {
                s[j] += __shfl_xor_sync(0xffffffffu, s[j], st);
                q[j] += __shfl_xor_sync(0xffffffffu, q[j], st);
            }
        }
        const int wid = tid >> 5, lane = tid & 31;
        if (lane == 0) {
#pragma unroll
            for (int j = 0; j < BT; ++j) { ssum[wid][j] = s[j]; sqq[wid][j] = q[j]; }
        }
        __syncthreads();
        if (tid < BT) {
            float ts = 0.f, tq = 0.f;
#pragma unroll
            for (int k = 0; k < 32; ++k) { ts += ssum[k][tid]; tq += sqq[k][tid]; }
            float* ps = (L == 1) ? g_ps1 : g_ps2;
            float* pq = (L == 1) ? g_pq1 : g_pq2;
            ps[chunk * B + btile * BT + tid] = ts;
            pq[chunk * B + btile * BT + tid] = tq;
        }
    } else {
        // fused final: group-sum of 16 consecutive outputs, minus 8
        const int lane = tid & 31;
#pragma unroll
        for (int st = 1; st < 16; st <<= 1) {
#pragma unroll
            for (int j = 0; j < 8; ++j)
                h0[j] += __shfl_xor_sync(0xffffffffu, h0[j], st);
        }
        if ((lane & 15) == 0) {
            const int g = o0 >> 4;
#pragma unroll
            for (int j = 0; j < 8; ++j)
                out[(btile * 8 + j) * 256 + g] = h0[j] - 8.0f;
        }
    }
}

// ---------------------------------------------------------------------------
extern "C" void kernel_launch(void* const* d_in, const int* in_sizes, int n_in,
                              void* d_out, int out_size) {
    (void)in_sizes; (void)n_in; (void)out_size;
    const float* x    = (const float*)d_in[0];
    const int*   sel1 = (const int*)  d_in[1];
    const float* w1   = (const float*)d_in[2];
    const float* b1   = (const float*)d_in[3];
    const float* g1   = (const float*)d_in[4];
    const float* be1  = (const float*)d_in[5];
    const int*   sel2 = (const int*)  d_in[6];
    const float* w2   = (const float*)d_in[7];
    const float* b2   = (const float*)d_in[8];
    const float* g2   = (const float*)d_in[9];
    const float* be2  = (const float*)d_in[10];
    const int*   sel3 = (const int*)  d_in[11];
    const float* w3   = (const float*)d_in[12];
    const float* b3   = (const float*)d_in[13];
    float* out = (float*)d_out;

    const int smem1 = IN1 * 16 * 2;   // 102400
    const int smem2 = O1  * 8  * 2;   // 131072
    cudaFuncSetAttribute(k_pop<1>, cudaFuncAttributeMaxDynamicSharedMemorySize, smem1);
    cudaFuncSetAttribute(k_pop<2>, cudaFuncAttributeMaxDynamicSharedMemorySize, smem2);
    cudaFuncSetAttribute(k_pop<3>, cudaFuncAttributeMaxDynamicSharedMemorySize, smem2);

    k_transpose<<<dim3(IN1 / 32, B / 32), dim3(32, 8)>>>(x);
    k_prep<<<640, 1024>>>(sel1, w1, sel2, w2, g1, be1, sel3, w3, g2, be2);

    k_pop<1><<<128, 1024, smem1>>>(b1, nullptr);   // 16 btiles x 8 chunks
    k_pop<2><<<128, 1024, smem2>>>(b2, nullptr);   // 32 btiles x 4 chunks
    k_pop<3><<<128, 1024, smem2>>>(b3, out);       // 32 btiles x 4 chunks
}